// round 10
// baseline (speedup 1.0000x reference)
#include <cuda_runtime.h>
#include <cuda_fp16.h>
#include <mma.h>
#include <cstdint>

using namespace nvcuda;

#define N_NODES 50000
#define N_EDGES 800000
#define D_IN    128
#define D_HID   512
#define D_OUT   128
#define D_CAT   (D_IN + D_HID)
#define SCAN_NB ((N_NODES + 255) / 256)   // 196
#define NCHUNK  4
#define CHUNK   12544                     // 98 * 128 (128-aligned)

// ---------------- device scratch (no allocations allowed) ----------------
__device__ __align__(16) __half g_Zh[(size_t)N_NODES * D_HID];   // relu(x@W+b) fp16
__device__ __align__(16) __half g_cat[(size_t)N_NODES * D_CAT];  // [Xh | agg_h]
__device__ __align__(16) __half g_Wh[(size_t)D_IN * D_HID];      // fc_w fp16
__device__ __align__(16) __half g_W2h[(size_t)D_CAT * D_OUT];    // weights fp16
__device__ __align__(16) int    g_counts[N_NODES];
__device__ __align__(16) int    g_offsets[N_NODES + 1];
__device__ __align__(16) int    g_cursor[N_NODES];
__device__ __align__(16) int    g_elist[N_EDGES];
__device__ __align__(16) unsigned long long g_aggpack[SCAN_NB];  // lookback state

// ---------------- zero counts + lookback state ----------------
__global__ __launch_bounds__(256) void zero_kernel() {
    int i = blockIdx.x * blockDim.x + threadIdx.x;
    if (i < N_NODES) g_counts[i] = 0;
    if (i < SCAN_NB) g_aggpack[i] = 0ULL;
}

// ---------------- CSR build (adjacency is int32 — proven in R2/R3) ----------------
__global__ void hist_kernel(const int* __restrict__ adj) {
    int e = blockIdx.x * blockDim.x + threadIdx.x;
    if (e < N_EDGES) {
        int src = adj[e];
        if ((unsigned)src < (unsigned)N_NODES)
            atomicAdd(&g_counts[src], 1);
    }
}

// single-pass exclusive scan with decoupled lookback (196 blocks, all co-resident)
__global__ __launch_bounds__(256) void scan_fused_kernel() {
    __shared__ int sm[256];
    __shared__ int pre[256];
    const int b = blockIdx.x;
    const int t = threadIdx.x;
    const int i = b * 256 + t;
    int v = (i < N_NODES) ? g_counts[i] : 0;
    sm[t] = v;
    __syncthreads();
    for (int off = 1; off < 256; off <<= 1) {
        int x = (t >= off) ? sm[t - off] : 0;
        __syncthreads();
        sm[t] += x;
        __syncthreads();
    }
    if (t == 0) {
        unsigned long long pk = (1ULL << 63) | (unsigned long long)(unsigned)sm[255];
        atomicExch(&g_aggpack[b], pk);
    }
    int myp = 0;
    if (t < b) {
        unsigned long long p;
        do { p = atomicAdd(&g_aggpack[t], 0ULL); } while (!(p >> 63));
        myp = (int)(p & 0xffffffffULL);
    }
    pre[t] = myp;
    __syncthreads();
    for (int off = 128; off > 0; off >>= 1) {
        if (t < off) pre[t] += pre[t + off];
        __syncthreads();
    }
    int bo = pre[0];
    if (i < N_NODES) {
        int excl = bo + sm[t] - v;
        g_offsets[i] = excl;
        g_cursor[i]  = excl;
        if (i == N_NODES - 1) g_offsets[N_NODES] = bo + sm[t];
    }
}

__global__ void scatter_kernel(const int* __restrict__ adj) {
    int e = blockIdx.x * blockDim.x + threadIdx.x;
    if (e < N_EDGES) {
        int src = adj[e];
        int trg = adj[N_EDGES + e];
        if ((unsigned)src < (unsigned)N_NODES && (unsigned)trg < (unsigned)N_NODES) {
            int pos = atomicAdd(&g_cursor[src], 1);
            if ((unsigned)pos < (unsigned)N_EDGES)
                g_elist[pos] = trg;
        }
    }
}

// ---------------- conversions to fp16 ----------------
#define CONV_X_VECS (N_NODES * D_IN / 8)             // 800000 uint4s
__global__ void conv_all_kernel(const float* __restrict__ X,
                                const float* __restrict__ fcw,
                                const float* __restrict__ w2) {
    int idx = blockIdx.x * blockDim.x + threadIdx.x;
    if (idx < CONV_X_VECS) {
        int i = idx * 8;
        int row = i >> 7;
        int col = i & 127;
        float4 a = *(const float4*)(X + i);
        float4 b = *(const float4*)(X + i + 4);
        union { __half h[8]; uint4 u; } pk;
        pk.h[0] = __float2half_rn(a.x); pk.h[1] = __float2half_rn(a.y);
        pk.h[2] = __float2half_rn(a.z); pk.h[3] = __float2half_rn(a.w);
        pk.h[4] = __float2half_rn(b.x); pk.h[5] = __float2half_rn(b.y);
        pk.h[6] = __float2half_rn(b.z); pk.h[7] = __float2half_rn(b.w);
        *(uint4*)(g_cat + (size_t)row * D_CAT + col) = pk.u;
    }
    if (idx < D_IN * D_HID) g_Wh[idx] = __float2half_rn(fcw[idx]);
    if (idx < D_CAT * D_OUT) g_W2h[idx] = __float2half_rn(w2[idx]);
}

// ---------------- Z = relu(Xh @ Wh + b), dual column tiles ----------------
__global__ __launch_bounds__(256) void gemm_relu_wmma(const float* __restrict__ bias) {
    __shared__ union SMem {
        struct { __half A[128 * 40]; __half B[2][32 * 72]; } t;
        float C[8 * 32 * 36];
    } sm;

    const int bm = blockIdx.y * 128;
    const int bn0 = blockIdx.x * 64;   // group 0: bn0, group 1: bn0+256
    const int tid = threadIdx.x;
    const int warp = tid >> 5;
    const int lane = tid & 31;
    const int wm = warp >> 1;
    const int wn = warp & 1;

    wmma::fragment<wmma::accumulator, 16, 16, 16, float> acc[2][2][2];
#pragma unroll
    for (int g = 0; g < 2; ++g)
#pragma unroll
        for (int i = 0; i < 2; ++i)
#pragma unroll
            for (int j = 0; j < 2; ++j) wmma::fill_fragment(acc[g][i][j], 0.f);

    for (int k0 = 0; k0 < D_IN; k0 += 32) {
#pragma unroll
        for (int r = 0; r < 2; ++r) {
            int f = tid + r * 256;
            int row = f >> 2, seg = f & 3;
            int gr = bm + row; if (gr >= N_NODES) gr = N_NODES - 1;
            *(uint4*)&sm.t.A[row * 40 + seg * 8] =
                *(const uint4*)(g_cat + (size_t)gr * D_CAT + k0 + seg * 8);
        }
        {
            int row = tid >> 3, seg = tid & 7;
#pragma unroll
            for (int g = 0; g < 2; ++g)
                *(uint4*)&sm.t.B[g][row * 72 + seg * 8] =
                    *(const uint4*)(g_Wh + (size_t)(k0 + row) * D_HID + bn0 + g * 256 + seg * 8);
        }
        __syncthreads();
#pragma unroll
        for (int kk = 0; kk < 2; ++kk) {
            wmma::fragment<wmma::matrix_a, 16, 16, 16, __half, wmma::row_major> af[2];
#pragma unroll
            for (int i = 0; i < 2; ++i)
                wmma::load_matrix_sync(af[i], &sm.t.A[(wm * 32 + i * 16) * 40 + kk * 16], 40);
#pragma unroll
            for (int g = 0; g < 2; ++g) {
                wmma::fragment<wmma::matrix_b, 16, 16, 16, __half, wmma::row_major> bf[2];
#pragma unroll
                for (int j = 0; j < 2; ++j)
                    wmma::load_matrix_sync(bf[j], &sm.t.B[g][(kk * 16) * 72 + wn * 32 + j * 16], 72);
#pragma unroll
                for (int i = 0; i < 2; ++i)
#pragma unroll
                    for (int j = 0; j < 2; ++j)
                        wmma::mma_sync(acc[g][i][j], af[i], bf[j], acc[g][i][j]);
            }
        }
        __syncthreads();
    }

    float* cw = &sm.C[warp * 32 * 36];
    int r = lane;
    int gr = bm + wm * 32 + r;
#pragma unroll
    for (int g = 0; g < 2; ++g) {
#pragma unroll
        for (int i = 0; i < 2; ++i)
#pragma unroll
            for (int j = 0; j < 2; ++j)
                wmma::store_matrix_sync(&cw[(i * 16) * 36 + j * 16], acc[g][i][j], 36, wmma::mem_row_major);
        __syncwarp();
        if (gr < N_NODES) {
            int cbase = bn0 + g * 256 + wn * 32;
            union { __half h[8]; uint4 u; } pk;
#pragma unroll
            for (int q = 0; q < 4; ++q) {
#pragma unroll
                for (int c = 0; c < 8; ++c) {
                    int col = q * 8 + c;
                    float v = cw[r * 36 + col] + bias[cbase + col];
                    pk.h[c] = __float2half_rn(fmaxf(v, 0.f));
                }
                *(uint4*)(g_Zh + (size_t)gr * D_HID + cbase + q * 8) = pk.u;
            }
        }
        __syncwarp();
    }
}

// ---------------- segment max over CSR, node range -> g_cat[:,128:640] ----------------
__global__ __launch_bounds__(128) void segmax_kernel(int node_base) {
    int n = node_base + blockIdx.x;
    if (n >= N_NODES) return;
    int t = threadIdx.x;
    int beg = g_offsets[n];
    int end = g_offsets[n + 1];

    __half2 m0 = __float2half2_rn(0.f);
    __half2 m1 = __float2half2_rn(0.f);

    int i = beg;
    for (; i + 7 < end; i += 8) {
        int e[8];
#pragma unroll
        for (int q = 0; q < 8; ++q) e[q] = g_elist[i + q];
        uint2 v[8];
#pragma unroll
        for (int q = 0; q < 8; ++q)
            v[q] = *(const uint2*)(g_Zh + (size_t)e[q] * D_HID + t * 4);
#pragma unroll
        for (int q = 0; q < 8; ++q) {
            m0 = __hmax2(m0, *(const __half2*)&v[q].x);
            m1 = __hmax2(m1, *(const __half2*)&v[q].y);
        }
    }
    for (; i + 1 < end; i += 2) {
        int e0 = g_elist[i];
        int e1 = g_elist[i + 1];
        uint2 v0 = *(const uint2*)(g_Zh + (size_t)e0 * D_HID + t * 4);
        uint2 v1 = *(const uint2*)(g_Zh + (size_t)e1 * D_HID + t * 4);
        m0 = __hmax2(m0, *(const __half2*)&v0.x);
        m1 = __hmax2(m1, *(const __half2*)&v0.y);
        m0 = __hmax2(m0, *(const __half2*)&v1.x);
        m1 = __hmax2(m1, *(const __half2*)&v1.y);
    }
    if (i < end) {
        int e0 = g_elist[i];
        uint2 v0 = *(const uint2*)(g_Zh + (size_t)e0 * D_HID + t * 4);
        m0 = __hmax2(m0, *(const __half2*)&v0.x);
        m1 = __hmax2(m1, *(const __half2*)&v0.y);
    }

    uint2 o;
    *(__half2*)&o.x = m0;
    *(__half2*)&o.y = m1;
    *(uint2*)(g_cat + (size_t)n * D_CAT + D_IN + t * 4) = o;
}

// ---------------- out = g_cat @ W2h (full K), row range ----------------
// BM=128, BN=128, BK=32, 8 warps 4(M)x2(N), warp tile 32x64.
__global__ __launch_bounds__(256) void gemm_out_wmma(float* __restrict__ out, int row_base) {
    __shared__ __half As[128 * 40];
    __shared__ __half Bs[32 * 136];

    const int bm = row_base + blockIdx.x * 128;
    const int tid = threadIdx.x;
    const int warp = tid >> 5;
    const int wm = warp >> 1;
    const int wn = warp & 1;

    wmma::fragment<wmma::accumulator, 16, 16, 16, float> acc[2][4];
#pragma unroll
    for (int i = 0; i < 2; ++i)
#pragma unroll
        for (int j = 0; j < 4; ++j) wmma::fill_fragment(acc[i][j], 0.f);

    for (int k0 = 0; k0 < D_CAT; k0 += 32) {
#pragma unroll
        for (int r = 0; r < 2; ++r) {
            int f = tid + r * 256;
            int row = f >> 2, seg = f & 3;
            int gr = bm + row; if (gr >= N_NODES) gr = N_NODES - 1;
            *(uint4*)&As[row * 40 + seg * 8] =
                *(const uint4*)(g_cat + (size_t)gr * D_CAT + k0 + seg * 8);
        }
#pragma unroll
        for (int r = 0; r < 2; ++r) {
            int f = tid + r * 256;
            int row = f >> 4, seg = f & 15;
            *(uint4*)&Bs[row * 136 + seg * 8] =
                *(const uint4*)(g_W2h + (size_t)(k0 + row) * D_OUT + seg * 8);
        }
        __syncthreads();
#pragma unroll
        for (int kk = 0; kk < 2; ++kk) {
            wmma::fragment<wmma::matrix_a, 16, 16, 16, __half, wmma::row_major> af[2];
            wmma::fragment<wmma::matrix_b, 16, 16, 16, __half, wmma::row_major> bf[4];
#pragma unroll
            for (int i = 0; i < 2; ++i)
                wmma::load_matrix_sync(af[i], &As[(wm * 32 + i * 16) * 40 + kk * 16], 40);
#pragma unroll
            for (int j = 0; j < 4; ++j)
                wmma::load_matrix_sync(bf[j], &Bs[(kk * 16) * 136 + wn * 64 + j * 16], 136);
#pragma unroll
            for (int i = 0; i < 2; ++i)
#pragma unroll
                for (int j = 0; j < 4; ++j)
                    wmma::mma_sync(acc[i][j], af[i], bf[j], acc[i][j]);
        }
        __syncthreads();
    }

#pragma unroll
    for (int i = 0; i < 2; ++i) {
        int gr0 = bm + wm * 32 + i * 16;
        if (gr0 + 16 <= N_NODES) {
#pragma unroll
            for (int j = 0; j < 4; ++j)
                wmma::store_matrix_sync(out + (size_t)gr0 * D_OUT + wn * 64 + j * 16,
                                        acc[i][j], D_OUT, wmma::mem_row_major);
        }
    }
}

// ---------------- launch ----------------
extern "C" void kernel_launch(void* const* d_in, const int* in_sizes, int n_in,
                              void* d_out, int out_size) {
    const float* input = nullptr;
    const float* fc_w  = nullptr;
    const float* fc_b  = nullptr;
    const float* w_out = nullptr;
    const int*   adj   = nullptr;
    for (int i = 0; i < n_in; ++i) {
        switch (in_sizes[i]) {
            case 6400000: input = (const float*)d_in[i]; break;
            case 65536:   fc_w  = (const float*)d_in[i]; break;
            case 512:     fc_b  = (const float*)d_in[i]; break;
            case 81920:   w_out = (const float*)d_in[i]; break;
            case 1600000: adj   = (const int*)d_in[i]; break;
            default: break;
        }
    }
    float* out = (float*)d_out;
    (void)out_size;
    if (!input || !fc_w || !fc_b || !w_out || !adj) return;

    cudaStream_t sCSR, sOut;
    cudaStreamCreateWithFlags(&sCSR, cudaStreamNonBlocking);
    cudaStreamCreateWithFlags(&sOut, cudaStreamNonBlocking);
    cudaEvent_t evFork, evCSR, evSeg[NCHUNK], evDone;
    cudaEventCreateWithFlags(&evFork, cudaEventDisableTiming);
    cudaEventCreateWithFlags(&evCSR, cudaEventDisableTiming);
    for (int c = 0; c < NCHUNK; ++c)
        cudaEventCreateWithFlags(&evSeg[c], cudaEventDisableTiming);
    cudaEventCreateWithFlags(&evDone, cudaEventDisableTiming);

    cudaEventRecord(evFork, 0);
    cudaStreamWaitEvent(sCSR, evFork, 0);

    // --- side stream: CSR build ---
    zero_kernel<<<SCAN_NB, 256, 0, sCSR>>>();
    hist_kernel<<<(N_EDGES + 255) / 256, 256, 0, sCSR>>>(adj);
    scan_fused_kernel<<<SCAN_NB, 256, 0, sCSR>>>();
    scatter_kernel<<<(N_EDGES + 255) / 256, 256, 0, sCSR>>>(adj);
    cudaEventRecord(evCSR, sCSR);

    // --- main stream: conversions + Z GEMM ---
    conv_all_kernel<<<(CONV_X_VECS + 255) / 256, 256>>>(input, fc_w, w_out);
    dim3 gA(4, (N_NODES + 127) / 128);
    gemm_relu_wmma<<<gA, 256>>>(fc_b);

    // --- segmax chunks on main stream, out GEMM chunks pipelined on sOut ---
    cudaStreamWaitEvent(0, evCSR, 0);
    for (int c = 0; c < NCHUNK; ++c) {
        int base = c * CHUNK;
        int count = (c == NCHUNK - 1) ? (N_NODES - base) : CHUNK;
        segmax_kernel<<<count, 128>>>(base);
        cudaEventRecord(evSeg[c], 0);
        cudaStreamWaitEvent(sOut, evSeg[c], 0);
        int tiles = (count + 127) / 128;
        gemm_out_wmma<<<tiles, 256, 0, sOut>>>(out, base);
    }
    cudaEventRecord(evDone, sOut);
    cudaStreamWaitEvent(0, evDone, 0);

    cudaEventDestroy(evFork);
    cudaEventDestroy(evCSR);
    for (int c = 0; c < NCHUNK; ++c) cudaEventDestroy(evSeg[c]);
    cudaEventDestroy(evDone);
    cudaStreamDestroy(sCSR);
    cudaStreamDestroy(sOut);
}

// round 11
// speedup vs baseline: 1.0698x; 1.0698x over previous
#include <cuda_runtime.h>
#include <cuda_fp16.h>
#include <mma.h>
#include <cstdint>

using namespace nvcuda;

#define N_NODES 50000
#define N_EDGES 800000
#define D_IN    128
#define D_HID   512
#define D_OUT   128
#define D_CAT   (D_IN + D_HID)
#define SCAN_NB ((N_NODES + 255) / 256)   // 196

// ---------------- device scratch (no allocations allowed) ----------------
__device__ __align__(16) __half g_Zh[(size_t)N_NODES * D_HID];   // relu(x@W+b) fp16
__device__ __align__(16) __half g_cat[(size_t)N_NODES * D_CAT];  // [Xh | agg_h]
__device__ __align__(16) __half g_Wh[(size_t)D_IN * D_HID];      // fc_w fp16
__device__ __align__(16) __half g_W2h[(size_t)D_CAT * D_OUT];    // weights fp16
__device__ __align__(16) int    g_counts[N_NODES];
__device__ __align__(16) int    g_offsets[N_NODES + 1];
__device__ __align__(16) int    g_cursor[N_NODES];
__device__ __align__(16) int    g_elist[N_EDGES];
__device__ __align__(16) unsigned long long g_aggpack[SCAN_NB];  // lookback state

// ---------------- zero counts + lookback state ----------------
__global__ __launch_bounds__(256) void zero_kernel() {
    int i = blockIdx.x * blockDim.x + threadIdx.x;
    if (i < N_NODES) g_counts[i] = 0;
    if (i < SCAN_NB) g_aggpack[i] = 0ULL;
}

// ---------------- CSR build (adjacency is int32 — proven in R2/R3) ----------------
// 4 edges per thread via int4 loads
__global__ void hist_kernel(const int* __restrict__ adj) {
    int q = blockIdx.x * blockDim.x + threadIdx.x;
    if (q * 4 < N_EDGES) {
        int4 s = *(const int4*)(adj + q * 4);
        if ((unsigned)s.x < (unsigned)N_NODES) atomicAdd(&g_counts[s.x], 1);
        if ((unsigned)s.y < (unsigned)N_NODES) atomicAdd(&g_counts[s.y], 1);
        if ((unsigned)s.z < (unsigned)N_NODES) atomicAdd(&g_counts[s.z], 1);
        if ((unsigned)s.w < (unsigned)N_NODES) atomicAdd(&g_counts[s.w], 1);
    }
}

// single-pass exclusive scan with decoupled lookback (196 blocks, all co-resident)
__global__ __launch_bounds__(256) void scan_fused_kernel() {
    __shared__ int sm[256];
    __shared__ int pre[256];
    const int b = blockIdx.x;
    const int t = threadIdx.x;
    const int i = b * 256 + t;
    int v = (i < N_NODES) ? g_counts[i] : 0;
    sm[t] = v;
    __syncthreads();
    for (int off = 1; off < 256; off <<= 1) {
        int x = (t >= off) ? sm[t - off] : 0;
        __syncthreads();
        sm[t] += x;
        __syncthreads();
    }
    if (t == 0) {
        unsigned long long pk = (1ULL << 63) | (unsigned long long)(unsigned)sm[255];
        atomicExch(&g_aggpack[b], pk);
    }
    int myp = 0;
    if (t < b) {
        unsigned long long p;
        do { p = atomicAdd(&g_aggpack[t], 0ULL); } while (!(p >> 63));
        myp = (int)(p & 0xffffffffULL);
    }
    pre[t] = myp;
    __syncthreads();
    for (int off = 128; off > 0; off >>= 1) {
        if (t < off) pre[t] += pre[t + off];
        __syncthreads();
    }
    int bo = pre[0];
    if (i < N_NODES) {
        int excl = bo + sm[t] - v;
        g_offsets[i] = excl;
        g_cursor[i]  = excl;
        if (i == N_NODES - 1) g_offsets[N_NODES] = bo + sm[t];
    }
}

// 4 edges per thread via int4 loads
__global__ void scatter_kernel(const int* __restrict__ adj) {
    int q = blockIdx.x * blockDim.x + threadIdx.x;
    if (q * 4 < N_EDGES) {
        int4 s = *(const int4*)(adj + q * 4);
        int4 d = *(const int4*)(adj + N_EDGES + q * 4);
        int ss[4] = {s.x, s.y, s.z, s.w};
        int dd[4] = {d.x, d.y, d.z, d.w};
#pragma unroll
        for (int k = 0; k < 4; ++k) {
            if ((unsigned)ss[k] < (unsigned)N_NODES && (unsigned)dd[k] < (unsigned)N_NODES) {
                int pos = atomicAdd(&g_cursor[ss[k]], 1);
                if ((unsigned)pos < (unsigned)N_EDGES)
                    g_elist[pos] = dd[k];
            }
        }
    }
}

// ---------------- conversions to fp16 ----------------
#define CONV_X_VECS (N_NODES * D_IN / 8)             // 800000 uint4s
__global__ void conv_all_kernel(const float* __restrict__ X,
                                const float* __restrict__ fcw,
                                const float* __restrict__ w2) {
    int idx = blockIdx.x * blockDim.x + threadIdx.x;
    if (idx < CONV_X_VECS) {
        int i = idx * 8;
        int row = i >> 7;
        int col = i & 127;
        float4 a = *(const float4*)(X + i);
        float4 b = *(const float4*)(X + i + 4);
        union { __half h[8]; uint4 u; } pk;
        pk.h[0] = __float2half_rn(a.x); pk.h[1] = __float2half_rn(a.y);
        pk.h[2] = __float2half_rn(a.z); pk.h[3] = __float2half_rn(a.w);
        pk.h[4] = __float2half_rn(b.x); pk.h[5] = __float2half_rn(b.y);
        pk.h[6] = __float2half_rn(b.z); pk.h[7] = __float2half_rn(b.w);
        *(uint4*)(g_cat + (size_t)row * D_CAT + col) = pk.u;
    }
    if (idx < D_IN * D_HID) g_Wh[idx] = __float2half_rn(fcw[idx]);
    if (idx < D_CAT * D_OUT) g_W2h[idx] = __float2half_rn(w2[idx]);
}

// ---------------- Z = relu(Xh @ Wh + b), dual column tiles ----------------
__global__ __launch_bounds__(256) void gemm_relu_wmma(const float* __restrict__ bias) {
    __shared__ union SMem {
        struct { __half A[128 * 40]; __half B[2][32 * 72]; } t;
        float C[8 * 32 * 36];
    } sm;

    const int bm = blockIdx.y * 128;
    const int bn0 = blockIdx.x * 64;   // group 0: bn0, group 1: bn0+256
    const int tid = threadIdx.x;
    const int warp = tid >> 5;
    const int lane = tid & 31;
    const int wm = warp >> 1;
    const int wn = warp & 1;

    wmma::fragment<wmma::accumulator, 16, 16, 16, float> acc[2][2][2];
#pragma unroll
    for (int g = 0; g < 2; ++g)
#pragma unroll
        for (int i = 0; i < 2; ++i)
#pragma unroll
            for (int j = 0; j < 2; ++j) wmma::fill_fragment(acc[g][i][j], 0.f);

    for (int k0 = 0; k0 < D_IN; k0 += 32) {
#pragma unroll
        for (int r = 0; r < 2; ++r) {
            int f = tid + r * 256;
            int row = f >> 2, seg = f & 3;
            int gr = bm + row; if (gr >= N_NODES) gr = N_NODES - 1;
            *(uint4*)&sm.t.A[row * 40 + seg * 8] =
                *(const uint4*)(g_cat + (size_t)gr * D_CAT + k0 + seg * 8);
        }
        {
            int row = tid >> 3, seg = tid & 7;
#pragma unroll
            for (int g = 0; g < 2; ++g)
                *(uint4*)&sm.t.B[g][row * 72 + seg * 8] =
                    *(const uint4*)(g_Wh + (size_t)(k0 + row) * D_HID + bn0 + g * 256 + seg * 8);
        }
        __syncthreads();
#pragma unroll
        for (int kk = 0; kk < 2; ++kk) {
            wmma::fragment<wmma::matrix_a, 16, 16, 16, __half, wmma::row_major> af[2];
#pragma unroll
            for (int i = 0; i < 2; ++i)
                wmma::load_matrix_sync(af[i], &sm.t.A[(wm * 32 + i * 16) * 40 + kk * 16], 40);
#pragma unroll
            for (int g = 0; g < 2; ++g) {
                wmma::fragment<wmma::matrix_b, 16, 16, 16, __half, wmma::row_major> bf[2];
#pragma unroll
                for (int j = 0; j < 2; ++j)
                    wmma::load_matrix_sync(bf[j], &sm.t.B[g][(kk * 16) * 72 + wn * 32 + j * 16], 72);
#pragma unroll
                for (int i = 0; i < 2; ++i)
#pragma unroll
                    for (int j = 0; j < 2; ++j)
                        wmma::mma_sync(acc[g][i][j], af[i], bf[j], acc[g][i][j]);
            }
        }
        __syncthreads();
    }

    float* cw = &sm.C[warp * 32 * 36];
    int r = lane;
    int gr = bm + wm * 32 + r;
#pragma unroll
    for (int g = 0; g < 2; ++g) {
#pragma unroll
        for (int i = 0; i < 2; ++i)
#pragma unroll
            for (int j = 0; j < 2; ++j)
                wmma::store_matrix_sync(&cw[(i * 16) * 36 + j * 16], acc[g][i][j], 36, wmma::mem_row_major);
        __syncwarp();
        if (gr < N_NODES) {
            int cbase = bn0 + g * 256 + wn * 32;
            union { __half h[8]; uint4 u; } pk;
#pragma unroll
            for (int q = 0; q < 4; ++q) {
#pragma unroll
                for (int c = 0; c < 8; ++c) {
                    int col = q * 8 + c;
                    float v = cw[r * 36 + col] + bias[cbase + col];
                    pk.h[c] = __float2half_rn(fmaxf(v, 0.f));
                }
                *(uint4*)(g_Zh + (size_t)gr * D_HID + cbase + q * 8) = pk.u;
            }
        }
        __syncwarp();
    }
}

// ---------------- segment max over CSR -> fp16, 2 nodes per 256-thread block ----------------
__global__ __launch_bounds__(256) void segmax_kernel() {
    int n = blockIdx.x * 2 + (threadIdx.x >> 7);
    int t = threadIdx.x & 127;
    int beg = g_offsets[n];
    int end = g_offsets[n + 1];

    __half2 m0 = __float2half2_rn(0.f);
    __half2 m1 = __float2half2_rn(0.f);

    int i = beg;
    for (; i + 7 < end; i += 8) {
        int e[8];
#pragma unroll
        for (int q = 0; q < 8; ++q) e[q] = g_elist[i + q];
        uint2 v[8];
#pragma unroll
        for (int q = 0; q < 8; ++q)
            v[q] = *(const uint2*)(g_Zh + (size_t)e[q] * D_HID + t * 4);
#pragma unroll
        for (int q = 0; q < 8; ++q) {
            m0 = __hmax2(m0, *(const __half2*)&v[q].x);
            m1 = __hmax2(m1, *(const __half2*)&v[q].y);
        }
    }
    for (; i + 1 < end; i += 2) {
        int e0 = g_elist[i];
        int e1 = g_elist[i + 1];
        uint2 v0 = *(const uint2*)(g_Zh + (size_t)e0 * D_HID + t * 4);
        uint2 v1 = *(const uint2*)(g_Zh + (size_t)e1 * D_HID + t * 4);
        m0 = __hmax2(m0, *(const __half2*)&v0.x);
        m1 = __hmax2(m1, *(const __half2*)&v0.y);
        m0 = __hmax2(m0, *(const __half2*)&v1.x);
        m1 = __hmax2(m1, *(const __half2*)&v1.y);
    }
    if (i < end) {
        int e0 = g_elist[i];
        uint2 v0 = *(const uint2*)(g_Zh + (size_t)e0 * D_HID + t * 4);
        m0 = __hmax2(m0, *(const __half2*)&v0.x);
        m1 = __hmax2(m1, *(const __half2*)&v0.y);
    }

    uint2 o;
    *(__half2*)&o.x = m0;
    *(__half2*)&o.y = m1;
    *(uint2*)(g_cat + (size_t)n * D_CAT + D_IN + t * 4) = o;
}

// ---------------- out partial GEMM over K range, optional accumulate ----------------
template<int KBEG, int KEND, int ACC>
__global__ __launch_bounds__(256) void gemm_out_part(float* __restrict__ out) {
    __shared__ __half As[128 * 40];
    __shared__ __half Bs[32 * 136];

    const int bm = blockIdx.x * 128;
    const int tid = threadIdx.x;
    const int warp = tid >> 5;
    const int wm = warp >> 1;
    const int wn = warp & 1;

    wmma::fragment<wmma::accumulator, 16, 16, 16, float> acc[2][4];
    if (ACC) {
#pragma unroll
        for (int i = 0; i < 2; ++i) {
            int gr0 = bm + wm * 32 + i * 16;
            if (gr0 + 16 <= N_NODES) {
#pragma unroll
                for (int j = 0; j < 4; ++j)
                    wmma::load_matrix_sync(acc[i][j],
                        out + (size_t)gr0 * D_OUT + wn * 64 + j * 16, D_OUT, wmma::mem_row_major);
            }
        }
    } else {
#pragma unroll
        for (int i = 0; i < 2; ++i)
#pragma unroll
            for (int j = 0; j < 4; ++j) wmma::fill_fragment(acc[i][j], 0.f);
    }

    for (int k0 = KBEG; k0 < KEND; k0 += 32) {
#pragma unroll
        for (int r = 0; r < 2; ++r) {
            int f = tid + r * 256;
            int row = f >> 2, seg = f & 3;
            int gr = bm + row; if (gr >= N_NODES) gr = N_NODES - 1;
            *(uint4*)&As[row * 40 + seg * 8] =
                *(const uint4*)(g_cat + (size_t)gr * D_CAT + k0 + seg * 8);
        }
#pragma unroll
        for (int r = 0; r < 2; ++r) {
            int f = tid + r * 256;
            int row = f >> 4, seg = f & 15;
            *(uint4*)&Bs[row * 136 + seg * 8] =
                *(const uint4*)(g_W2h + (size_t)(k0 + row) * D_OUT + seg * 8);
        }
        __syncthreads();
#pragma unroll
        for (int kk = 0; kk < 2; ++kk) {
            wmma::fragment<wmma::matrix_a, 16, 16, 16, __half, wmma::row_major> af[2];
            wmma::fragment<wmma::matrix_b, 16, 16, 16, __half, wmma::row_major> bf[4];
#pragma unroll
            for (int i = 0; i < 2; ++i)
                wmma::load_matrix_sync(af[i], &As[(wm * 32 + i * 16) * 40 + kk * 16], 40);
#pragma unroll
            for (int j = 0; j < 4; ++j)
                wmma::load_matrix_sync(bf[j], &Bs[(kk * 16) * 136 + wn * 64 + j * 16], 136);
#pragma unroll
            for (int i = 0; i < 2; ++i)
#pragma unroll
                for (int j = 0; j < 4; ++j)
                    wmma::mma_sync(acc[i][j], af[i], bf[j], acc[i][j]);
        }
        __syncthreads();
    }

#pragma unroll
    for (int i = 0; i < 2; ++i) {
        int gr0 = bm + wm * 32 + i * 16;
        if (gr0 + 16 <= N_NODES) {
#pragma unroll
            for (int j = 0; j < 4; ++j)
                wmma::store_matrix_sync(out + (size_t)gr0 * D_OUT + wn * 64 + j * 16,
                                        acc[i][j], D_OUT, wmma::mem_row_major);
        }
    }
}

// ---------------- launch ----------------
extern "C" void kernel_launch(void* const* d_in, const int* in_sizes, int n_in,
                              void* d_out, int out_size) {
    const float* input = nullptr;
    const float* fc_w  = nullptr;
    const float* fc_b  = nullptr;
    const float* w_out = nullptr;
    const int*   adj   = nullptr;
    for (int i = 0; i < n_in; ++i) {
        switch (in_sizes[i]) {
            case 6400000: input = (const float*)d_in[i]; break;
            case 65536:   fc_w  = (const float*)d_in[i]; break;
            case 512:     fc_b  = (const float*)d_in[i]; break;
            case 81920:   w_out = (const float*)d_in[i]; break;
            case 1600000: adj   = (const int*)d_in[i]; break;
            default: break;
        }
    }
    float* out = (float*)d_out;
    (void)out_size;
    if (!input || !fc_w || !fc_b || !w_out || !adj) return;

    cudaStream_t sCSR, sX;
    cudaStreamCreateWithFlags(&sCSR, cudaStreamNonBlocking);
    cudaStreamCreateWithFlags(&sX, cudaStreamNonBlocking);
    cudaEvent_t evFork, evCSR, evConv, evOutX;
    cudaEventCreateWithFlags(&evFork, cudaEventDisableTiming);
    cudaEventCreateWithFlags(&evCSR, cudaEventDisableTiming);
    cudaEventCreateWithFlags(&evConv, cudaEventDisableTiming);
    cudaEventCreateWithFlags(&evOutX, cudaEventDisableTiming);

    cudaEventRecord(evFork, 0);
    cudaStreamWaitEvent(sCSR, evFork, 0);

    // --- side stream 1: CSR build ---
    zero_kernel<<<SCAN_NB, 256, 0, sCSR>>>();
    hist_kernel<<<(N_EDGES / 4 + 255) / 256, 256, 0, sCSR>>>(adj);
    scan_fused_kernel<<<SCAN_NB, 256, 0, sCSR>>>();
    scatter_kernel<<<(N_EDGES / 4 + 255) / 256, 256, 0, sCSR>>>(adj);
    cudaEventRecord(evCSR, sCSR);

    // --- main stream: conversions + Z GEMM ---
    conv_all_kernel<<<(CONV_X_VECS + 255) / 256, 256>>>(input, fc_w, w_out);
    cudaEventRecord(evConv, 0);
    dim3 gA(4, (N_NODES + 127) / 128);
    gemm_relu_wmma<<<gA, 256>>>(fc_b);

    // --- side stream 2: out X-part (needs only conv) ---
    cudaStreamWaitEvent(sX, evConv, 0);
    gemm_out_part<0, D_IN, 0><<<(N_NODES + 127) / 128, 256, 0, sX>>>(out);
    cudaEventRecord(evOutX, sX);

    // --- segmax (needs CSR + Z) ---
    cudaStreamWaitEvent(0, evCSR, 0);
    segmax_kernel<<<N_NODES / 2, 256>>>();

    // --- out agg-part, accumulating into out ---
    cudaStreamWaitEvent(0, evOutX, 0);
    gemm_out_part<D_IN, D_CAT, 1><<<(N_NODES + 127) / 128, 256>>>(out);

    cudaEventDestroy(evFork);
    cudaEventDestroy(evCSR);
    cudaEventDestroy(evConv);
    cudaEventDestroy(evOutX);
    cudaStreamDestroy(sCSR);
    cudaStreamDestroy(sX);
}